// round 1
// baseline (speedup 1.0000x reference)
#include <cuda_runtime.h>
#include <math.h>

// ---------------------------------------------------------------------------
// Problem constants
// ---------------------------------------------------------------------------
static constexpr int BATCH = 256;   // per-text batch
static constexpr int SEQ   = 128;   // timesteps
static constexpr int HID   = 512;   // hidden size H
static constexpr int G4    = 2048;  // 4*H gate width
static constexpr int BB    = 768;   // combined batch (3 texts)

// ---------------------------------------------------------------------------
// Scratch (device globals; no runtime allocation allowed)
// ---------------------------------------------------------------------------
__device__ float g_seqA[(size_t)BB * SEQ * HID];   // 201 MB
__device__ float g_seqB[(size_t)BB * SEQ * HID];   // 201 MB
__device__ float g_gx  [(size_t)BB * SEQ * G4];    // 805 MB  (x-part gates, all timesteps)
__device__ float g_ghh [(size_t)BB * G4];          // h-part gates for current step
__device__ float g_h   [(size_t)BB * HID];
__device__ float g_c   [(size_t)BB * HID];
__device__ float g_xn1 [BATCH * 1536];
__device__ float g_a1  [BATCH * 1024];
__device__ float g_xn2 [BATCH * 1024];
__device__ float g_W2p [1024 * 128];               // W2 zero-padded 102 -> 128 cols
__device__ float g_b2p [128];
__device__ float g_a2  [BATCH * 128];
__device__ float g_a2n [BATCH * 128];

// ---------------------------------------------------------------------------
// Embedding gather: seqA[(s*256+b)*SEQ + t][:] = emb[text_s[b,t]][:]
// grid = BB*SEQ blocks, 128 threads (one float4 per thread)
// ---------------------------------------------------------------------------
__global__ void embed_kernel(const int* __restrict__ t1, const int* __restrict__ t2,
                             const int* __restrict__ t3, const float* __restrict__ emb,
                             float* __restrict__ out) {
    int bbt = blockIdx.x;
    int bb  = bbt >> 7;          // / SEQ
    int t   = bbt & 127;
    int s   = bb >> 8;           // / BATCH
    int b   = bb & 255;
    const int* txt = (s == 0) ? t1 : (s == 1 ? t2 : t3);
    int tok = txt[b * SEQ + t];
    const float4* src = (const float4*)(emb + (size_t)tok * HID);
    float4*       dst = (float4*)(out + (size_t)bbt * HID);
    dst[threadIdx.x] = src[threadIdx.x];
}

// ---------------------------------------------------------------------------
// SELU
// ---------------------------------------------------------------------------
__device__ __forceinline__ float selu_f(float x) {
    const float sc = 1.0507009873554805f;
    const float al = 1.6732632423543772f;
    return x > 0.f ? sc * x : sc * al * expm1f(x);
}

// ---------------------------------------------------------------------------
// Tiled fp32 GEMM: C[M,N] = A[M,K] @ B[K,N] (+bias) (+selu)
// Requires M%128==0, N%128==0, K%16==0. 128x128 tile, 256 thr, 8x8 micro-tile.
// ---------------------------------------------------------------------------
template <bool BIAS, bool SELU>
__global__ void __launch_bounds__(256, 2)
sgemm128(const float* __restrict__ A, const float* __restrict__ B,
         float* __restrict__ C, int M, int N, int K,
         const float* __restrict__ bias) {
    __shared__ float As[16][128];
    __shared__ float Bs[16][128];

    const int bm  = blockIdx.y * 128;
    const int bn  = blockIdx.x * 128;
    const int tid = threadIdx.x;
    const int tx  = (tid & 15) * 8;   // N offset inside tile
    const int ty  = (tid >> 4) * 8;   // M offset inside tile

    float acc[8][8] = {};

    const int arow = tid >> 2;          // 0..63
    const int acol = (tid & 3) << 2;    // 0,4,8,12
    const int brow = tid >> 5;          // 0..7
    const int bcol = (tid & 31) << 2;   // 0..124

    const float* Aptr = A + (size_t)(bm + arow) * K + acol;
    const float* Bptr = B + (size_t)brow * N + bn + bcol;

    for (int k0 = 0; k0 < K; k0 += 16) {
        float4 a0 = *(const float4*)(Aptr);
        float4 a1 = *(const float4*)(Aptr + (size_t)64 * K);
        float4 b0 = *(const float4*)(Bptr);
        float4 b1 = *(const float4*)(Bptr + (size_t)8 * N);

        As[acol + 0][arow]      = a0.x;
        As[acol + 1][arow]      = a0.y;
        As[acol + 2][arow]      = a0.z;
        As[acol + 3][arow]      = a0.w;
        As[acol + 0][arow + 64] = a1.x;
        As[acol + 1][arow + 64] = a1.y;
        As[acol + 2][arow + 64] = a1.z;
        As[acol + 3][arow + 64] = a1.w;
        *(float4*)&Bs[brow][bcol]     = b0;
        *(float4*)&Bs[brow + 8][bcol] = b1;
        __syncthreads();

        #pragma unroll
        for (int kk = 0; kk < 16; kk++) {
            float ar[8], br[8];
            *(float4*)(ar)     = *(const float4*)&As[kk][ty];
            *(float4*)(ar + 4) = *(const float4*)&As[kk][ty + 4];
            *(float4*)(br)     = *(const float4*)&Bs[kk][tx];
            *(float4*)(br + 4) = *(const float4*)&Bs[kk][tx + 4];
            #pragma unroll
            for (int i = 0; i < 8; i++)
                #pragma unroll
                for (int j = 0; j < 8; j++)
                    acc[i][j] += ar[i] * br[j];
        }
        __syncthreads();

        Aptr += 16;
        Bptr += (size_t)16 * N;
    }

    float bv[8];
    if (BIAS) {
        #pragma unroll
        for (int j = 0; j < 8; j++) bv[j] = bias[bn + tx + j];
    }

    #pragma unroll
    for (int i = 0; i < 8; i++) {
        float v[8];
        #pragma unroll
        for (int j = 0; j < 8; j++) {
            float x = acc[i][j];
            if (BIAS) x += bv[j];
            if (SELU) x = selu_f(x);
            v[j] = x;
        }
        float* crow = C + (size_t)(bm + ty + i) * N + bn + tx;
        *(float4*)(crow)     = *(float4*)(v);
        *(float4*)(crow + 4) = *(float4*)(v + 4);
    }
}

// ---------------------------------------------------------------------------
// LSTM cell update (gate order i, j, f, o; forget_bias = 0)
// grid covers BB*HID elements.
// ---------------------------------------------------------------------------
__global__ void lstm_cell(const float* __restrict__ gx, const float* __restrict__ ghh,
                          float* __restrict__ c, float* __restrict__ h,
                          float* __restrict__ seq_out, int t) {
    int idx = blockIdx.x * 256 + threadIdx.x;   // < BB*HID
    int bb  = idx >> 9;
    int j   = idx & 511;
    size_t gb = ((size_t)bb * SEQ + t) * G4 + j;
    size_t hb = (size_t)bb * G4 + j;

    float zi = gx[gb]        + ghh[hb];
    float zj = gx[gb + 512]  + ghh[hb + 512];
    float zf = gx[gb + 1024] + ghh[hb + 1024];
    float zo = gx[gb + 1536] + ghh[hb + 1536];

    float ig = 1.f / (1.f + expf(-zi));
    float fg = 1.f / (1.f + expf(-zf));
    float og = 1.f / (1.f + expf(-zo));

    float cn = fg * c[idx] + ig * tanhf(zj);
    float hn = og * tanhf(cn);

    c[idx] = cn;
    h[idx] = hn;
    seq_out[((size_t)bb * SEQ + t) * HID + j] = hn;
}

// ---------------------------------------------------------------------------
// BatchNorm over batch dim (256 rows). bn1 reads the concat-rep layout
// directly from the final hidden state h: rep[b, s*512+j] = h[(s*256+b)*512+j]
// One block per feature, 256 threads = 256 rows. Two-pass mean/var.
// ---------------------------------------------------------------------------
__global__ void bn1_kernel(const float* __restrict__ h, const float* __restrict__ gamma,
                           const float* __restrict__ beta, float* __restrict__ y) {
    int f = blockIdx.x;              // 0..1535
    int r = threadIdx.x;             // 0..255 (batch row)
    int s = f >> 9;
    int j = f & 511;
    float v = h[((size_t)(s * BATCH + r)) * HID + j];

    __shared__ float sd[256];
    sd[r] = v; __syncthreads();
    for (int w = 128; w > 0; w >>= 1) { if (r < w) sd[r] += sd[r + w]; __syncthreads(); }
    float mu = sd[0] * (1.f / 256.f);
    __syncthreads();
    float d = v - mu;
    sd[r] = d * d; __syncthreads();
    for (int w = 128; w > 0; w >>= 1) { if (r < w) sd[r] += sd[r + w]; __syncthreads(); }
    float var = sd[0] * (1.f / 256.f);

    float sc = gamma[f] * rsqrtf(var + 1e-3f);
    y[r * 1536 + f] = d * sc + beta[f];
}

__global__ void bn_kernel(const float* __restrict__ x, const float* __restrict__ gamma,
                          const float* __restrict__ beta, float* __restrict__ y,
                          int stride) {
    int f = blockIdx.x;
    int r = threadIdx.x;
    float v = x[(size_t)r * stride + f];

    __shared__ float sd[256];
    sd[r] = v; __syncthreads();
    for (int w = 128; w > 0; w >>= 1) { if (r < w) sd[r] += sd[r + w]; __syncthreads(); }
    float mu = sd[0] * (1.f / 256.f);
    __syncthreads();
    float d = v - mu;
    sd[r] = d * d; __syncthreads();
    for (int w = 128; w > 0; w >>= 1) { if (r < w) sd[r] += sd[r + w]; __syncthreads(); }
    float var = sd[0] * (1.f / 256.f);

    float sc = gamma[f] * rsqrtf(var + 1e-3f);
    y[(size_t)r * stride + f] = d * sc + beta[f];
}

// ---------------------------------------------------------------------------
// Pad W2 [1024,102] -> [1024,128] (zeros), b2 -> b2p[128]
// ---------------------------------------------------------------------------
__global__ void pad_w2(const float* __restrict__ W2, const float* __restrict__ b2,
                       float* __restrict__ w2p, float* __restrict__ b2p) {
    int idx = blockIdx.x * 256 + threadIdx.x;   // < 1024*128
    int n = idx & 127;
    int k = idx >> 7;
    w2p[idx] = (n < 102) ? W2[k * 102 + n] : 0.f;
    if (idx < 128) b2p[idx] = (idx < 102) ? b2[idx] : 0.f;
}

// ---------------------------------------------------------------------------
// Final tiny GEMM: out[256,4] = a2n[256,102 (stride 128)] @ W3[102,4] + b3
// ---------------------------------------------------------------------------
__global__ void out_kernel(const float* __restrict__ a, const float* __restrict__ W3,
                           const float* __restrict__ b3, float* __restrict__ out) {
    int idx = blockIdx.x * 256 + threadIdx.x;   // < 1024
    int b = idx >> 2;
    int n = idx & 3;
    float acc = b3[n];
    #pragma unroll 6
    for (int k = 0; k < 102; k++)
        acc += a[b * 128 + k] * W3[k * 4 + n];
    out[idx] = acc;
}

// ---------------------------------------------------------------------------
// Launch
// ---------------------------------------------------------------------------
extern "C" void kernel_launch(void* const* d_in, const int* in_sizes, int n_in,
                              void* d_out, int out_size) {
    const int*   t1   = (const int*)d_in[0];
    const int*   t2   = (const int*)d_in[1];
    const int*   t3   = (const int*)d_in[2];
    const float* emb  = (const float*)d_in[3];
    const float* lw   = (const float*)d_in[4];   // [3, 1024, 2048]
    const float* lb   = (const float*)d_in[5];   // [3, 2048]
    const float* bn1g = (const float*)d_in[6];
    const float* bn1b = (const float*)d_in[7];
    const float* W1   = (const float*)d_in[8];   // [1536, 1024]
    const float* b1   = (const float*)d_in[9];
    const float* bn2g = (const float*)d_in[10];
    const float* bn2b = (const float*)d_in[11];
    const float* W2   = (const float*)d_in[12];  // [1024, 102]
    const float* b2   = (const float*)d_in[13];
    const float* bn3g = (const float*)d_in[14];
    const float* bn3b = (const float*)d_in[15];
    const float* W3   = (const float*)d_in[16];  // [102, 4]
    const float* b3   = (const float*)d_in[17];
    float* out = (float*)d_out;

    float *seqA, *seqB, *gx, *ghh, *h, *c, *xn1, *a1, *xn2, *w2p, *b2p, *a2, *a2n;
    cudaGetSymbolAddress((void**)&seqA, g_seqA);
    cudaGetSymbolAddress((void**)&seqB, g_seqB);
    cudaGetSymbolAddress((void**)&gx,   g_gx);
    cudaGetSymbolAddress((void**)&ghh,  g_ghh);
    cudaGetSymbolAddress((void**)&h,    g_h);
    cudaGetSymbolAddress((void**)&c,    g_c);
    cudaGetSymbolAddress((void**)&xn1,  g_xn1);
    cudaGetSymbolAddress((void**)&a1,   g_a1);
    cudaGetSymbolAddress((void**)&xn2,  g_xn2);
    cudaGetSymbolAddress((void**)&w2p,  g_W2p);
    cudaGetSymbolAddress((void**)&b2p,  g_b2p);
    cudaGetSymbolAddress((void**)&a2,   g_a2);
    cudaGetSymbolAddress((void**)&a2n,  g_a2n);

    // 1) Embedding gather for all 3 texts into combined sequence buffer.
    embed_kernel<<<BB * SEQ, 128>>>(t1, t2, t3, emb, seqA);

    // 2) 3 LSTM layers over the combined batch of 768 sequences.
    float* cur = seqA;
    float* nxt = seqB;
    for (int l = 0; l < 3; l++) {
        const float* Wx = lw + (size_t)l * 1024 * G4;        // rows [0,512)
        const float* Wh = Wx + (size_t)HID * G4;             // rows [512,1024)
        const float* bl = lb + (size_t)l * G4;

        // Input-gate precompute for every timestep (one big parallel GEMM).
        sgemm128<true, false><<<dim3(G4 / 128, (BB * SEQ) / 128), 256>>>(
            cur, Wx, gx, BB * SEQ, G4, HID, bl);

        cudaMemsetAsync(h, 0, (size_t)BB * HID * sizeof(float), 0);
        cudaMemsetAsync(c, 0, (size_t)BB * HID * sizeof(float), 0);

        // Sequential recurrence.
        for (int t = 0; t < SEQ; t++) {
            sgemm128<false, false><<<dim3(G4 / 128, BB / 128), 256>>>(
                h, Wh, ghh, BB, G4, HID, nullptr);
            lstm_cell<<<(BB * HID) / 256, 256>>>(gx, ghh, c, h, nxt, t);
        }
        float* tmp = cur; cur = nxt; nxt = tmp;
    }
    // After layer 3, g_h holds the final top-layer hidden state for all 768
    // sequences (== rep before BN1, with rep[b, s*512+j] = h[s*256+b][j]).

    // 3) Head.
    bn1_kernel<<<1536, 256>>>(h, bn1g, bn1b, xn1);
    sgemm128<true, true><<<dim3(1024 / 128, BATCH / 128), 256>>>(
        xn1, W1, a1, BATCH, 1024, 1536, b1);
    bn_kernel<<<1024, 256>>>(a1, bn2g, bn2b, xn2, 1024);
    pad_w2<<<(1024 * 128) / 256, 256>>>(W2, b2, w2p, b2p);
    sgemm128<true, true><<<dim3(1, BATCH / 128), 256>>>(
        xn2, w2p, a2, BATCH, 128, 1024, b2p);
    bn_kernel<<<102, 256>>>(a2, bn3g, bn3b, a2n, 128);
    out_kernel<<<4, 256>>>(a2n, W3, b3, out);
}

// round 2
// speedup vs baseline: 1.1906x; 1.1906x over previous
#include <cuda_runtime.h>
#include <math.h>
#include <stdint.h>

// ---------------------------------------------------------------------------
// Problem constants
// ---------------------------------------------------------------------------
static constexpr int BATCH = 256;   // per-text batch
static constexpr int SEQ   = 128;   // timesteps
static constexpr int HID   = 512;   // hidden size H
static constexpr int G4    = 2048;  // 4*H gate width
static constexpr int BB    = 768;   // combined batch (3 texts)

// ---------------------------------------------------------------------------
// Scratch (device globals; no runtime allocation allowed)
// ---------------------------------------------------------------------------
__device__ float g_seqA[(size_t)BB * SEQ * HID];   // 201 MB
__device__ float g_seqB[(size_t)BB * SEQ * HID];   // 201 MB
__device__ float g_gx  [(size_t)BB * SEQ * G4];    // 805 MB (x-part gates, interleaved layout)
__device__ float g_h1  [(size_t)BB * HID];
__device__ float g_h2  [(size_t)BB * HID];
__device__ float g_c   [(size_t)BB * HID];
__device__ float g_Wxp [(size_t)3 * HID * G4];     // gate-interleaved Wx per layer
__device__ float g_Whp [(size_t)3 * HID * G4];     // gate-interleaved Wh per layer
__device__ float g_bp  [3 * G4];                   // gate-interleaved bias
__device__ float g_xn1 [BATCH * 1536];
__device__ float g_a1  [BATCH * 1024];
__device__ float g_xn2 [BATCH * 1024];
__device__ float g_W2p [1024 * 128];
__device__ float g_b2p [128];
__device__ float g_a2  [BATCH * 128];
__device__ float g_a2n [BATCH * 128];

// ---------------------------------------------------------------------------
// TF32 helpers
// ---------------------------------------------------------------------------
__device__ __forceinline__ uint32_t tf32r(float x) {
    uint32_t u;
    asm("cvt.rna.tf32.f32 %0, %1;" : "=r"(u) : "f"(x));
    return u;
}

__device__ __forceinline__ void mma8(float* c, const uint32_t* a, const uint32_t* b) {
    asm volatile(
        "mma.sync.aligned.m16n8k8.row.col.f32.tf32.tf32.f32 "
        "{%0,%1,%2,%3}, {%4,%5,%6,%7}, {%8,%9}, {%0,%1,%2,%3};"
        : "+f"(c[0]), "+f"(c[1]), "+f"(c[2]), "+f"(c[3])
        : "r"(a[0]), "r"(a[1]), "r"(a[2]), "r"(a[3]), "r"(b[0]), "r"(b[1]));
}

// ---------------------------------------------------------------------------
// Embedding gather
// ---------------------------------------------------------------------------
__global__ void embed_kernel(const int* __restrict__ t1, const int* __restrict__ t2,
                             const int* __restrict__ t3, const float* __restrict__ emb,
                             float* __restrict__ out) {
    int bbt = blockIdx.x;
    int bb  = bbt >> 7;
    int t   = bbt & 127;
    int s   = bb >> 8;
    int b   = bb & 255;
    const int* txt = (s == 0) ? t1 : (s == 1 ? t2 : t3);
    int tok = txt[b * SEQ + t];
    const float4* src = (const float4*)(emb + (size_t)tok * HID);
    float4*       dst = (float4*)(out + (size_t)bbt * HID);
    dst[threadIdx.x] = src[threadIdx.x];
}

// ---------------------------------------------------------------------------
// Weight/bias permutation into gate-interleaved layout:
//   W'[k][4u+g] = W[k][g*512+u],  b'[4u+g] = b[g*512+u]
// ---------------------------------------------------------------------------
__global__ void prep_kernel(const float* __restrict__ lw, const float* __restrict__ lb,
                            float* __restrict__ wxp, float* __restrict__ whp,
                            float* __restrict__ bp) {
    int idx = blockIdx.x * 256 + threadIdx.x;       // < 3*1024*2048
    int l   = idx / (1024 * G4);
    int rem = idx - l * 1024 * G4;
    int k   = rem / G4;
    int n   = rem - k * G4;
    int u   = n >> 2, g = n & 3;
    float v = lw[(size_t)l * 1024 * G4 + (size_t)k * G4 + g * HID + u];
    if (k < HID) wxp[(size_t)l * HID * G4 + (size_t)k * G4 + n] = v;
    else         whp[(size_t)l * HID * G4 + (size_t)(k - HID) * G4 + n] = v;
    if (idx < 3 * G4) {
        int ll = idx / G4, nn = idx - ll * G4;
        bp[idx] = lb[ll * G4 + (nn & 3) * HID + (nn >> 2)];
    }
}

// ---------------------------------------------------------------------------
// Big parallel GEMM (tf32 tensor cores):
//   C[M,2048] = A[M,512] @ B[512,2048] + bias   (M = BB*SEQ, multiple of 128)
// 128x128 CTA tile, 8 warps (4x2), warp tile 32x64 (m16n8k8 frags 2x8).
// ---------------------------------------------------------------------------
__global__ void __launch_bounds__(256, 2)
gemm_x_tf32(const float* __restrict__ A, const float* __restrict__ B,
            const float* __restrict__ bias, float* __restrict__ C) {
    __shared__ uint32_t As[128][33];
    __shared__ uint32_t Bs[32][129];

    const int tid  = threadIdx.x;
    const int lane = tid & 31, warp = tid >> 5;
    const int wm   = (warp >> 1) * 32, wn = (warp & 1) * 64;
    const int bm   = blockIdx.y * 128, bn = blockIdx.x * 128;

    float acc[2][8][4] = {};

    const int alr = tid >> 3,  alc = (tid & 7) << 2;    // A: 32 rows/pass, 4 passes
    const int blr = tid >> 5,  blc = (tid & 31) << 2;   // B: 8 rows/pass, 4 passes

    for (int kt = 0; kt < 512; kt += 32) {
        #pragma unroll
        for (int p = 0; p < 4; p++) {
            int r = alr + p * 32;
            float4 v = *(const float4*)(A + (size_t)(bm + r) * 512 + kt + alc);
            As[r][alc + 0] = tf32r(v.x); As[r][alc + 1] = tf32r(v.y);
            As[r][alc + 2] = tf32r(v.z); As[r][alc + 3] = tf32r(v.w);
        }
        #pragma unroll
        for (int p = 0; p < 4; p++) {
            int r = blr + p * 8;
            float4 v = *(const float4*)(B + (size_t)(kt + r) * G4 + bn + blc);
            Bs[r][blc + 0] = tf32r(v.x); Bs[r][blc + 1] = tf32r(v.y);
            Bs[r][blc + 2] = tf32r(v.z); Bs[r][blc + 3] = tf32r(v.w);
        }
        __syncthreads();

        #pragma unroll
        for (int ks = 0; ks < 4; ks++) {
            const int k0 = ks * 8;
            uint32_t af[2][4], bf[8][2];
            #pragma unroll
            for (int mf = 0; mf < 2; mf++) {
                int r = wm + mf * 16 + (lane >> 2), c = k0 + (lane & 3);
                af[mf][0] = As[r][c];     af[mf][1] = As[r + 8][c];
                af[mf][2] = As[r][c + 4]; af[mf][3] = As[r + 8][c + 4];
            }
            #pragma unroll
            for (int nf = 0; nf < 8; nf++) {
                int n = wn + nf * 8 + (lane >> 2);
                bf[nf][0] = Bs[k0 + (lane & 3)][n];
                bf[nf][1] = Bs[k0 + 4 + (lane & 3)][n];
            }
            #pragma unroll
            for (int mf = 0; mf < 2; mf++)
                #pragma unroll
                for (int nf = 0; nf < 8; nf++)
                    mma8(acc[mf][nf], af[mf], bf[nf]);
        }
        __syncthreads();
    }

    const int q = lane & 3;
    #pragma unroll
    for (int mf = 0; mf < 2; mf++) {
        int r0 = bm + wm + mf * 16 + (lane >> 2);
        #pragma unroll
        for (int nf = 0; nf < 8; nf++) {
            int n = bn + wn + nf * 8 + 2 * q;
            float b0 = bias[n], b1 = bias[n + 1];
            float2 v0 = make_float2(acc[mf][nf][0] + b0, acc[mf][nf][1] + b1);
            float2 v1 = make_float2(acc[mf][nf][2] + b0, acc[mf][nf][3] + b1);
            *(float2*)(C + (size_t)r0 * G4 + n)       = v0;
            *(float2*)(C + (size_t)(r0 + 8) * G4 + n) = v1;
        }
    }
}

// ---------------------------------------------------------------------------
// Fused recurrent step (tf32 tensor cores + LSTM cell epilogue):
//   zh[768,2048] = h_in[768,512] @ Wh'[512,2048]; z = zh + gx[:,t,:];
//   cell update in-epilogue (gate-interleaved columns, shfl pair exchange).
// 64x128 CTA tile, 4 warps (2x2), warp tile 32x64. Grid 16x12 = 192 CTAs.
// ---------------------------------------------------------------------------
__global__ void __launch_bounds__(128, 2)
lstm_step(const float* __restrict__ h_in, const float* __restrict__ Wh,
          const float* __restrict__ gx, float* __restrict__ c_st,
          float* __restrict__ h_out, float* __restrict__ seq_out, int t) {
    __shared__ uint32_t As[64][33];
    __shared__ uint32_t Bs[32][129];

    const int tid  = threadIdx.x;
    const int lane = tid & 31, warp = tid >> 5;
    const int wm   = (warp >> 1) * 32, wn = (warp & 1) * 64;
    const int bm   = blockIdx.y * 64, bn = blockIdx.x * 128;

    float acc[2][8][4] = {};

    const int alr = tid >> 3,  alc = (tid & 7) << 2;    // A: 16 rows/pass, 4 passes
    const int blr = tid >> 5,  blc = (tid & 31) << 2;   // B: 4 rows/pass, 8 passes

    for (int kt = 0; kt < 512; kt += 32) {
        #pragma unroll
        for (int p = 0; p < 4; p++) {
            int r = alr + p * 16;
            float4 v = *(const float4*)(h_in + (size_t)(bm + r) * HID + kt + alc);
            As[r][alc + 0] = tf32r(v.x); As[r][alc + 1] = tf32r(v.y);
            As[r][alc + 2] = tf32r(v.z); As[r][alc + 3] = tf32r(v.w);
        }
        #pragma unroll
        for (int p = 0; p < 8; p++) {
            int r = blr + p * 4;
            float4 v = *(const float4*)(Wh + (size_t)(kt + r) * G4 + bn + blc);
            Bs[r][blc + 0] = tf32r(v.x); Bs[r][blc + 1] = tf32r(v.y);
            Bs[r][blc + 2] = tf32r(v.z); Bs[r][blc + 3] = tf32r(v.w);
        }
        __syncthreads();

        #pragma unroll
        for (int ks = 0; ks < 4; ks++) {
            const int k0 = ks * 8;
            uint32_t af[2][4], bf[8][2];
            #pragma unroll
            for (int mf = 0; mf < 2; mf++) {
                int r = wm + mf * 16 + (lane >> 2), c = k0 + (lane & 3);
                af[mf][0] = As[r][c];     af[mf][1] = As[r + 8][c];
                af[mf][2] = As[r][c + 4]; af[mf][3] = As[r + 8][c + 4];
            }
            #pragma unroll
            for (int nf = 0; nf < 8; nf++) {
                int n = wn + nf * 8 + (lane >> 2);
                bf[nf][0] = Bs[k0 + (lane & 3)][n];
                bf[nf][1] = Bs[k0 + 4 + (lane & 3)][n];
            }
            #pragma unroll
            for (int mf = 0; mf < 2; mf++)
                #pragma unroll
                for (int nf = 0; nf < 8; nf++)
                    mma8(acc[mf][nf], af[mf], bf[nf]);
        }
        __syncthreads();
    }

    // Epilogue: gate-interleaved cell update.
    // Column 4u+g holds gate g (i,j,f,o) of hidden unit u. Thread pair
    // (lane, lane^1) holds (i,j)/(f,o) for the same unit; exchange via shfl.
    const int q = lane & 3;
    #pragma unroll
    for (int mf = 0; mf < 2; mf++) {
        int r0 = bm + wm + mf * 16 + (lane >> 2);
        int r1 = r0 + 8;
        #pragma unroll
        for (int nf = 0; nf < 8; nf++) {
            int ncol = bn + wn + nf * 8 + 2 * q;
            float2 ga = *(const float2*)(gx + ((size_t)r0 * SEQ + t) * G4 + ncol);
            float2 gb = *(const float2*)(gx + ((size_t)r1 * SEQ + t) * G4 + ncol);
            float z0 = acc[mf][nf][0] + ga.x;
            float z1 = acc[mf][nf][1] + ga.y;
            float z2 = acc[mf][nf][2] + gb.x;
            float z3 = acc[mf][nf][3] + gb.y;
            float o0 = __shfl_xor_sync(0xffffffffu, z0, 1);
            float o1 = __shfl_xor_sync(0xffffffffu, z1, 1);
            float o2 = __shfl_xor_sync(0xffffffffu, z2, 1);
            float o3 = __shfl_xor_sync(0xffffffffu, z3, 1);
            bool evenq = (q & 1) == 0;
            int   row = evenq ? r0 : r1;
            float zi  = evenq ? z0 : o2;
            float zj  = evenq ? z1 : o3;
            float zf  = evenq ? o0 : z2;
            float zo  = evenq ? o1 : z3;
            int   u   = ncol >> 2;

            float ig = 1.f / (1.f + expf(-zi));
            float fg = 1.f / (1.f + expf(-zf));
            float og = 1.f / (1.f + expf(-zo));
            size_t ci = (size_t)row * HID + u;
            float cn = fg * c_st[ci] + ig * tanhf(zj);
            float hn = og * tanhf(cn);
            c_st[ci]  = cn;
            h_out[ci] = hn;
            seq_out[((size_t)row * SEQ + t) * HID + u] = hn;
        }
    }
}

// ---------------------------------------------------------------------------
// SELU
// ---------------------------------------------------------------------------
__device__ __forceinline__ float selu_f(float x) {
    const float sc = 1.0507009873554805f;
    const float al = 1.6732632423543772f;
    return x > 0.f ? sc * x : sc * al * expm1f(x);
}

// ---------------------------------------------------------------------------
// Head fp32 GEMM (tiny) — unchanged from round 1
// ---------------------------------------------------------------------------
template <bool BIAS, bool SELU>
__global__ void __launch_bounds__(256, 2)
sgemm128(const float* __restrict__ A, const float* __restrict__ B,
         float* __restrict__ C, int M, int N, int K,
         const float* __restrict__ bias) {
    __shared__ float As[16][128];
    __shared__ float Bs[16][128];

    const int bm  = blockIdx.y * 128;
    const int bn  = blockIdx.x * 128;
    const int tid = threadIdx.x;
    const int tx  = (tid & 15) * 8;
    const int ty  = (tid >> 4) * 8;

    float acc[8][8] = {};

    const int arow = tid >> 2;
    const int acol = (tid & 3) << 2;
    const int brow = tid >> 5;
    const int bcol = (tid & 31) << 2;

    const float* Aptr = A + (size_t)(bm + arow) * K + acol;
    const float* Bptr = B + (size_t)brow * N + bn + bcol;

    for (int k0 = 0; k0 < K; k0 += 16) {
        float4 a0 = *(const float4*)(Aptr);
        float4 a1 = *(const float4*)(Aptr + (size_t)64 * K);
        float4 b0 = *(const float4*)(Bptr);
        float4 b1 = *(const float4*)(Bptr + (size_t)8 * N);

        As[acol + 0][arow]      = a0.x;
        As[acol + 1][arow]      = a0.y;
        As[acol + 2][arow]      = a0.z;
        As[acol + 3][arow]      = a0.w;
        As[acol + 0][arow + 64] = a1.x;
        As[acol + 1][arow + 64] = a1.y;
        As[acol + 2][arow + 64] = a1.z;
        As[acol + 3][arow + 64] = a1.w;
        *(float4*)&Bs[brow][bcol]     = b0;
        *(float4*)&Bs[brow + 8][bcol] = b1;
        __syncthreads();

        #pragma unroll
        for (int kk = 0; kk < 16; kk++) {
            float ar[8], br[8];
            *(float4*)(ar)     = *(const float4*)&As[kk][ty];
            *(float4*)(ar + 4) = *(const float4*)&As[kk][ty + 4];
            *(float4*)(br)     = *(const float4*)&Bs[kk][tx];
            *(float4*)(br + 4) = *(const float4*)&Bs[kk][tx + 4];
            #pragma unroll
            for (int i = 0; i < 8; i++)
                #pragma unroll
                for (int j = 0; j < 8; j++)
                    acc[i][j] += ar[i] * br[j];
        }
        __syncthreads();

        Aptr += 16;
        Bptr += (size_t)16 * N;
    }

    float bv[8];
    if (BIAS) {
        #pragma unroll
        for (int j = 0; j < 8; j++) bv[j] = bias[bn + tx + j];
    }

    #pragma unroll
    for (int i = 0; i < 8; i++) {
        float v[8];
        #pragma unroll
        for (int j = 0; j < 8; j++) {
            float x = acc[i][j];
            if (BIAS) x += bv[j];
            if (SELU) x = selu_f(x);
            v[j] = x;
        }
        float* crow = C + (size_t)(bm + ty + i) * N + bn + tx;
        *(float4*)(crow)     = *(float4*)(v);
        *(float4*)(crow + 4) = *(float4*)(v + 4);
    }
}

// ---------------------------------------------------------------------------
// BatchNorm kernels
// ---------------------------------------------------------------------------
__global__ void bn1_kernel(const float* __restrict__ h, const float* __restrict__ gamma,
                           const float* __restrict__ beta, float* __restrict__ y) {
    int f = blockIdx.x;
    int r = threadIdx.x;
    int s = f >> 9;
    int j = f & 511;
    float v = h[((size_t)(s * BATCH + r)) * HID + j];

    __shared__ float sd[256];
    sd[r] = v; __syncthreads();
    for (int w = 128; w > 0; w >>= 1) { if (r < w) sd[r] += sd[r + w]; __syncthreads(); }
    float mu = sd[0] * (1.f / 256.f);
    __syncthreads();
    float d = v - mu;
    sd[r] = d * d; __syncthreads();
    for (int w = 128; w > 0; w >>= 1) { if (r < w) sd[r] += sd[r + w]; __syncthreads(); }
    float var = sd[0] * (1.f / 256.f);

    float sc = gamma[f] * rsqrtf(var + 1e-3f);
    y[r * 1536 + f] = d * sc + beta[f];
}

__global__ void bn_kernel(const float* __restrict__ x, const float* __restrict__ gamma,
                          const float* __restrict__ beta, float* __restrict__ y,
                          int stride) {
    int f = blockIdx.x;
    int r = threadIdx.x;
    float v = x[(size_t)r * stride + f];

    __shared__ float sd[256];
    sd[r] = v; __syncthreads();
    for (int w = 128; w > 0; w >>= 1) { if (r < w) sd[r] += sd[r + w]; __syncthreads(); }
    float mu = sd[0] * (1.f / 256.f);
    __syncthreads();
    float d = v - mu;
    sd[r] = d * d; __syncthreads();
    for (int w = 128; w > 0; w >>= 1) { if (r < w) sd[r] += sd[r + w]; __syncthreads(); }
    float var = sd[0] * (1.f / 256.f);

    float sc = gamma[f] * rsqrtf(var + 1e-3f);
    y[(size_t)r * stride + f] = d * sc + beta[f];
}

__global__ void pad_w2(const float* __restrict__ W2, const float* __restrict__ b2,
                       float* __restrict__ w2p, float* __restrict__ b2p) {
    int idx = blockIdx.x * 256 + threadIdx.x;
    int n = idx & 127;
    int k = idx >> 7;
    w2p[idx] = (n < 102) ? W2[k * 102 + n] : 0.f;
    if (idx < 128) b2p[idx] = (idx < 102) ? b2[idx] : 0.f;
}

__global__ void out_kernel(const float* __restrict__ a, const float* __restrict__ W3,
                           const float* __restrict__ b3, float* __restrict__ out) {
    int idx = blockIdx.x * 256 + threadIdx.x;
    int b = idx >> 2;
    int n = idx & 3;
    float acc = b3[n];
    #pragma unroll 6
    for (int k = 0; k < 102; k++)
        acc += a[b * 128 + k] * W3[k * 4 + n];
    out[idx] = acc;
}

// ---------------------------------------------------------------------------
// Launch
// ---------------------------------------------------------------------------
extern "C" void kernel_launch(void* const* d_in, const int* in_sizes, int n_in,
                              void* d_out, int out_size) {
    const int*   t1   = (const int*)d_in[0];
    const int*   t2   = (const int*)d_in[1];
    const int*   t3   = (const int*)d_in[2];
    const float* emb  = (const float*)d_in[3];
    const float* lw   = (const float*)d_in[4];
    const float* lb   = (const float*)d_in[5];
    const float* bn1g = (const float*)d_in[6];
    const float* bn1b = (const float*)d_in[7];
    const float* W1   = (const float*)d_in[8];
    const float* b1   = (const float*)d_in[9];
    const float* bn2g = (const float*)d_in[10];
    const float* bn2b = (const float*)d_in[11];
    const float* W2   = (const float*)d_in[12];
    const float* b2   = (const float*)d_in[13];
    const float* bn3g = (const float*)d_in[14];
    const float* bn3b = (const float*)d_in[15];
    const float* W3   = (const float*)d_in[16];
    const float* b3   = (const float*)d_in[17];
    float* out = (float*)d_out;

    float *seqA, *seqB, *gx, *h1, *h2, *c, *wxp, *whp, *bp;
    float *xn1, *a1, *xn2, *w2p, *b2p, *a2, *a2n;
    cudaGetSymbolAddress((void**)&seqA, g_seqA);
    cudaGetSymbolAddress((void**)&seqB, g_seqB);
    cudaGetSymbolAddress((void**)&gx,   g_gx);
    cudaGetSymbolAddress((void**)&h1,   g_h1);
    cudaGetSymbolAddress((void**)&h2,   g_h2);
    cudaGetSymbolAddress((void**)&c,    g_c);
    cudaGetSymbolAddress((void**)&wxp,  g_Wxp);
    cudaGetSymbolAddress((void**)&whp,  g_Whp);
    cudaGetSymbolAddress((void**)&bp,   g_bp);
    cudaGetSymbolAddress((void**)&xn1,  g_xn1);
    cudaGetSymbolAddress((void**)&a1,   g_a1);
    cudaGetSymbolAddress((void**)&xn2,  g_xn2);
    cudaGetSymbolAddress((void**)&w2p,  g_W2p);
    cudaGetSymbolAddress((void**)&b2p,  g_b2p);
    cudaGetSymbolAddress((void**)&a2,   g_a2);
    cudaGetSymbolAddress((void**)&a2n,  g_a2n);

    // Weight permutation (gate-interleave) + embedding gather.
    prep_kernel<<<(3 * 1024 * G4) / 256, 256>>>(lw, lb, wxp, whp, bp);
    embed_kernel<<<BB * SEQ, 128>>>(t1, t2, t3, emb, seqA);

    float* cur = seqA;
    float* nxt = seqB;
    for (int l = 0; l < 3; l++) {
        const float* Wxl = wxp + (size_t)l * HID * G4;
        const float* Whl = whp + (size_t)l * HID * G4;
        const float* bl  = bp + l * G4;

        // Parallel x-part gates for all timesteps (tensor cores).
        gemm_x_tf32<<<dim3(G4 / 128, (BB * SEQ) / 128), 256>>>(cur, Wxl, bl, gx);

        cudaMemsetAsync(h1, 0, (size_t)BB * HID * sizeof(float), 0);
        cudaMemsetAsync(c,  0, (size_t)BB * HID * sizeof(float), 0);

        // Fused recurrent steps (double-buffered h; SEQ even -> final in h1).
        for (int t = 0; t < SEQ; t++) {
            const float* hi = (t & 1) ? h2 : h1;
            float*       ho = (t & 1) ? h1 : h2;
            lstm_step<<<dim3(G4 / 128, BB / 64), 128>>>(hi, Whl, gx, c, ho, nxt, t);
        }
        float* tmp = cur; cur = nxt; nxt = tmp;
    }

    // Head (final hidden state of top layer is in h1).
    bn1_kernel<<<1536, 256>>>(h1, bn1g, bn1b, xn1);
    sgemm128<true, true><<<dim3(1024 / 128, BATCH / 128), 256>>>(
        xn1, W1, a1, BATCH, 1024, 1536, b1);
    bn_kernel<<<1024, 256>>>(a1, bn2g, bn2b, xn2, 1024);
    pad_w2<<<(1024 * 128) / 256, 256>>>(W2, b2, w2p, b2p);
    sgemm128<true, true><<<dim3(1, BATCH / 128), 256>>>(
        xn2, w2p, a2, BATCH, 128, 1024, b2p);
    bn_kernel<<<102, 256>>>(a2, bn3g, bn3b, a2n, 128);
    out_kernel<<<4, 256>>>(a2n, W3, b3, out);
}

// round 3
// speedup vs baseline: 1.9994x; 1.6794x over previous
#include <cuda_runtime.h>
#include <math.h>
#include <stdint.h>

// ---------------------------------------------------------------------------
// Problem constants
// ---------------------------------------------------------------------------
static constexpr int BATCH = 256;
static constexpr int SEQ   = 128;
static constexpr int HID   = 512;
static constexpr int G4    = 2048;
static constexpr int BB    = 768;

// Persistent recurrence config
static constexpr int NCTA    = 128;            // 4 M-blocks x 32 N-slices
static constexpr int M_TILE  = 192;
static constexpr int N_TILE  = 64;
static constexpr int SMEM_B_WORDS = 64 * 512;          // packed B: kg(64) x 512
static constexpr int SMEM_A_WORDS = 2 * 4 * M_TILE * 8; // 2 bufs x kg(4) x 192*8
static constexpr int SMEM_C_WORDS = M_TILE * 16;
static constexpr int SMEM_WORDS   = SMEM_B_WORDS + SMEM_A_WORDS + SMEM_C_WORDS;
static constexpr int SMEM_BYTES   = SMEM_WORDS * 4;    // 192512

// ---------------------------------------------------------------------------
// Scratch (device globals; no runtime allocation allowed)
// ---------------------------------------------------------------------------
__device__ float g_seqA[(size_t)BB * SEQ * HID];
__device__ float g_seqB[(size_t)BB * SEQ * HID];
__device__ float g_gx  [(size_t)BB * SEQ * G4];
__device__ float g_h1  [(size_t)BB * HID];
__device__ float g_h2  [(size_t)BB * HID];
__device__ float g_Wxp [(size_t)3 * HID * G4];
__device__ float g_Whp [(size_t)3 * HID * G4];
__device__ float g_bp  [3 * G4];
__device__ float g_xn1 [BATCH * 1536];
__device__ float g_a1  [BATCH * 1024];
__device__ float g_xn2 [BATCH * 1024];
__device__ float g_W2p [1024 * 128];
__device__ float g_b2p [128];
__device__ float g_a2  [BATCH * 128];
__device__ float g_a2n [BATCH * 128];

// Grid barrier state (monotonic phase; replay/graph safe)
__device__ unsigned int g_bar_count;
__device__ unsigned int g_bar_phase;

// ---------------------------------------------------------------------------
// TF32 helpers
// ---------------------------------------------------------------------------
__device__ __forceinline__ uint32_t tf32r(float x) {
    uint32_t u;
    asm("cvt.rna.tf32.f32 %0, %1;" : "=r"(u) : "f"(x));
    return u;
}

__device__ __forceinline__ void mma8(float* c, const uint32_t* a, const uint32_t* b) {
    asm volatile(
        "mma.sync.aligned.m16n8k8.row.col.f32.tf32.tf32.f32 "
        "{%0,%1,%2,%3}, {%4,%5,%6,%7}, {%8,%9}, {%0,%1,%2,%3};"
        : "+f"(c[0]), "+f"(c[1]), "+f"(c[2]), "+f"(c[3])
        : "r"(a[0]), "r"(a[1]), "r"(a[2]), "r"(a[3]), "r"(b[0]), "r"(b[1]));
}

__device__ __forceinline__ unsigned int ld_acq(const unsigned int* p) {
    unsigned int v;
    asm volatile("ld.acquire.gpu.u32 %0, [%1];" : "=r"(v) : "l"(p));
    return v;
}

// ---------------------------------------------------------------------------
// Embedding gather
// ---------------------------------------------------------------------------
__global__ void embed_kernel(const int* __restrict__ t1, const int* __restrict__ t2,
                             const int* __restrict__ t3, const float* __restrict__ emb,
                             float* __restrict__ out) {
    int bbt = blockIdx.x;
    int bb  = bbt >> 7;
    int t   = bbt & 127;
    int s   = bb >> 8;
    int b   = bb & 255;
    const int* txt = (s == 0) ? t1 : (s == 1 ? t2 : t3);
    int tok = txt[b * SEQ + t];
    const float4* src = (const float4*)(emb + (size_t)tok * HID);
    float4*       dst = (float4*)(out + (size_t)bbt * HID);
    dst[threadIdx.x] = src[threadIdx.x];
}

// ---------------------------------------------------------------------------
// Weight/bias permutation into gate-interleaved layout
// ---------------------------------------------------------------------------
__global__ void prep_kernel(const float* __restrict__ lw, const float* __restrict__ lb,
                            float* __restrict__ wxp, float* __restrict__ whp,
                            float* __restrict__ bp) {
    int idx = blockIdx.x * 256 + threadIdx.x;
    int l   = idx / (1024 * G4);
    int rem = idx - l * 1024 * G4;
    int k   = rem / G4;
    int n   = rem - k * G4;
    int u   = n >> 2, g = n & 3;
    float v = lw[(size_t)l * 1024 * G4 + (size_t)k * G4 + g * HID + u];
    if (k < HID) wxp[(size_t)l * HID * G4 + (size_t)k * G4 + n] = v;
    else         whp[(size_t)l * HID * G4 + (size_t)(k - HID) * G4 + n] = v;
    if (idx < 3 * G4) {
        int ll = idx / G4, nn = idx - ll * G4;
        bp[idx] = lb[ll * G4 + (nn & 3) * HID + (nn >> 2)];
    }
}

// ---------------------------------------------------------------------------
// Big parallel x-GEMM (tf32 tensor cores), unchanged from round 2
// ---------------------------------------------------------------------------
__global__ void __launch_bounds__(256, 2)
gemm_x_tf32(const float* __restrict__ A, const float* __restrict__ B,
            const float* __restrict__ bias, float* __restrict__ C) {
    __shared__ uint32_t As[128][33];
    __shared__ uint32_t Bs[32][129];

    const int tid  = threadIdx.x;
    const int lane = tid & 31, warp = tid >> 5;
    const int wm   = (warp >> 1) * 32, wn = (warp & 1) * 64;
    const int bm   = blockIdx.y * 128, bn = blockIdx.x * 128;

    float acc[2][8][4] = {};

    const int alr = tid >> 3,  alc = (tid & 7) << 2;
    const int blr = tid >> 5,  blc = (tid & 31) << 2;

    for (int kt = 0; kt < 512; kt += 32) {
        #pragma unroll
        for (int p = 0; p < 4; p++) {
            int r = alr + p * 32;
            float4 v = *(const float4*)(A + (size_t)(bm + r) * 512 + kt + alc);
            As[r][alc + 0] = tf32r(v.x); As[r][alc + 1] = tf32r(v.y);
            As[r][alc + 2] = tf32r(v.z); As[r][alc + 3] = tf32r(v.w);
        }
        #pragma unroll
        for (int p = 0; p < 4; p++) {
            int r = blr + p * 8;
            float4 v = *(const float4*)(B + (size_t)(kt + r) * G4 + bn + blc);
            Bs[r][blc + 0] = tf32r(v.x); Bs[r][blc + 1] = tf32r(v.y);
            Bs[r][blc + 2] = tf32r(v.z); Bs[r][blc + 3] = tf32r(v.w);
        }
        __syncthreads();

        #pragma unroll
        for (int ks = 0; ks < 4; ks++) {
            const int k0 = ks * 8;
            uint32_t af[2][4], bf[8][2];
            #pragma unroll
            for (int mf = 0; mf < 2; mf++) {
                int r = wm + mf * 16 + (lane >> 2), c = k0 + (lane & 3);
                af[mf][0] = As[r][c];     af[mf][1] = As[r + 8][c];
                af[mf][2] = As[r][c + 4]; af[mf][3] = As[r + 8][c + 4];
            }
            #pragma unroll
            for (int nf = 0; nf < 8; nf++) {
                int n = wn + nf * 8 + (lane >> 2);
                bf[nf][0] = Bs[k0 + (lane & 3)][n];
                bf[nf][1] = Bs[k0 + 4 + (lane & 3)][n];
            }
            #pragma unroll
            for (int mf = 0; mf < 2; mf++)
                #pragma unroll
                for (int nf = 0; nf < 8; nf++)
                    mma8(acc[mf][nf], af[mf], bf[nf]);
        }
        __syncthreads();
    }

    const int q = lane & 3;
    #pragma unroll
    for (int mf = 0; mf < 2; mf++) {
        int r0 = bm + wm + mf * 16 + (lane >> 2);
        #pragma unroll
        for (int nf = 0; nf < 8; nf++) {
            int n = bn + wn + nf * 8 + 2 * q;
            float b0 = bias[n], b1 = bias[n + 1];
            float2 v0 = make_float2(acc[mf][nf][0] + b0, acc[mf][nf][1] + b1);
            float2 v1 = make_float2(acc[mf][nf][2] + b0, acc[mf][nf][3] + b1);
            *(float2*)(C + (size_t)r0 * G4 + n)       = v0;
            *(float2*)(C + (size_t)(r0 + 8) * G4 + n) = v1;
        }
    }
}

// ---------------------------------------------------------------------------
// Persistent LSTM layer: all 128 timesteps in one launch.
// 128 CTAs (1/SM, co-resident), 256 threads. Each CTA: 192x64 output tile.
// Wh slice (512x64) packed in SMEM for the whole layer; c-state in SMEM;
// h ping-pongs in global (L2 via __ldcg); software grid barrier per step.
// ---------------------------------------------------------------------------
__global__ void __launch_bounds__(256, 1)
lstm_layer(const float* __restrict__ Wh, const float* __restrict__ gx,
           float* __restrict__ hb0, float* __restrict__ hb1,
           float* __restrict__ seq_out) {
    extern __shared__ uint32_t smem[];
    uint32_t* Bp  = smem;                                  // packed B frags
    uint32_t* Ap  = smem + SMEM_B_WORDS;                   // 2 x A chunk
    float*    csm = (float*)(smem + SMEM_B_WORDS + SMEM_A_WORDS);

    const int tid  = threadIdx.x;
    const int lane = tid & 31, warp = tid >> 5;
    const int q    = lane & 3;
    const int p    = lane >> 2;
    const int wm   = (warp >> 1) * 48;      // warp M offset (local)
    const int wn   = (warp & 1) * 32;       // warp N offset (local)
    const int m0   = (blockIdx.x >> 5) * M_TILE;
    const int n0   = (blockIdx.x & 31) * N_TILE;

    unsigned int phase = 0;
    if (tid == 0) phase = ld_acq(&g_bar_phase);

    // --- Load + pack B slice (once per layer) -------------------------------
    for (int i = tid; i < 512 * 16; i += 256) {            // 8192 float4 slots
        int k = i >> 4, cg = i & 15;
        float4 v = *(const float4*)(Wh + (size_t)k * G4 + n0 + cg * 4);
        int kg = k >> 3, kk = k & 7;
        int base = kg * 512 + (kk & 3) * 2 + (kk >> 2);
        Bp[base + (cg * 4 + 0) * 8] = tf32r(v.x);
        Bp[base + (cg * 4 + 1) * 8] = tf32r(v.y);
        Bp[base + (cg * 4 + 2) * 8] = tf32r(v.z);
        Bp[base + (cg * 4 + 3) * 8] = tf32r(v.w);
    }
    for (int i = tid; i < SMEM_C_WORDS; i += 256) csm[i] = 0.f;
    __syncthreads();

    float* hbuf[2] = {hb0, hb1};

    for (int t = 0; t < SEQ; t++) {
        const float* hin  = hbuf[t & 1];
        float*       hout = hbuf[(t + 1) & 1];

        float acc[3][4][4] = {};

        if (t > 0) {
            // prologue: load chunk 0
            float4 v[6];
            #pragma unroll
            for (int i = 0; i < 6; i++) {
                int s = tid + i * 256;
                int row = s >> 3, cg = s & 7;
                v[i] = __ldcg((const float4*)(hin + (size_t)(m0 + row) * HID + cg * 4));
            }
            #pragma unroll 1
            for (int ct = 0; ct < 16; ct++) {
                uint32_t* Ab = Ap + (ct & 1) * (4 * M_TILE * 8);
                // pack-store current chunk
                #pragma unroll
                for (int i = 0; i < 6; i++) {
                    int s = tid + i * 256;
                    int row = s >> 3, cg = s & 7;
                    float vv[4] = {v[i].x, v[i].y, v[i].z, v[i].w};
                    #pragma unroll
                    for (int j = 0; j < 4; j++) {
                        int kl  = cg * 4 + j;
                        int kgl = kl >> 3, kk = kl & 7;
                        Ab[kgl * (M_TILE * 8) + row * 8 + (kk & 3) * 2 + (kk >> 2)] = tf32r(vv[j]);
                    }
                }
                __syncthreads();
                // prefetch next chunk
                if (ct < 15) {
                    int kt = (ct + 1) * 32;
                    #pragma unroll
                    for (int i = 0; i < 6; i++) {
                        int s = tid + i * 256;
                        int row = s >> 3, cg = s & 7;
                        v[i] = __ldcg((const float4*)(hin + (size_t)(m0 + row) * HID + kt + cg * 4));
                    }
                }
                // mma over 4 k-groups of this chunk
                #pragma unroll
                for (int kgl = 0; kgl < 4; kgl++) {
                    const int kg = ct * 4 + kgl;
                    uint32_t af[3][4];
                    #pragma unroll
                    for (int mf = 0; mf < 3; mf++) {
                        int rl = wm + mf * 16 + p;
                        uint2 p0 = *(const uint2*)&Ab[kgl * (M_TILE * 8) + rl * 8 + q * 2];
                        uint2 p1 = *(const uint2*)&Ab[kgl * (M_TILE * 8) + (rl + 8) * 8 + q * 2];
                        af[mf][0] = p0.x; af[mf][1] = p1.x; af[mf][2] = p0.y; af[mf][3] = p1.y;
                    }
                    uint32_t bfr[4][2];
                    #pragma unroll
                    for (int nf = 0; nf < 4; nf++) {
                        int nl = wn + nf * 8 + p;
                        uint2 pb = *(const uint2*)&Bp[kg * 512 + nl * 8 + q * 2];
                        bfr[nf][0] = pb.x; bfr[nf][1] = pb.y;
                    }
                    #pragma unroll
                    for (int mf = 0; mf < 3; mf++)
                        #pragma unroll
                        for (int nf = 0; nf < 4; nf++)
                            mma8(acc[mf][nf], af[mf], bfr[nf]);
                }
                __syncthreads();
            }
        }

        // --- epilogue: z = acc + gx; LSTM cell; c in SMEM -------------------
        #pragma unroll
        for (int mf = 0; mf < 3; mf++) {
            int rl0 = wm + mf * 16 + p;
            int rl1 = rl0 + 8;
            #pragma unroll
            for (int nf = 0; nf < 4; nf++) {
                int ncl = wn + nf * 8 + 2 * q;
                float2 ga = *(const float2*)(gx + ((size_t)(m0 + rl0) * SEQ + t) * G4 + n0 + ncl);
                float2 gb = *(const float2*)(gx + ((size_t)(m0 + rl1) * SEQ + t) * G4 + n0 + ncl);
                float z0 = acc[mf][nf][0] + ga.x;
                float z1 = acc[mf][nf][1] + ga.y;
                float z2 = acc[mf][nf][2] + gb.x;
                float z3 = acc[mf][nf][3] + gb.y;
                float o0 = __shfl_xor_sync(0xffffffffu, z0, 1);
                float o1 = __shfl_xor_sync(0xffffffffu, z1, 1);
                float o2 = __shfl_xor_sync(0xffffffffu, z2, 1);
                float o3 = __shfl_xor_sync(0xffffffffu, z3, 1);
                bool evenq = (q & 1) == 0;
                int   rl = evenq ? rl0 : rl1;
                float zi = evenq ? z0 : o2;
                float zj = evenq ? z1 : o3;
                float zf = evenq ? o0 : z2;
                float zo = evenq ? o1 : z3;
                int   ul = ncl >> 2;

                float ig = 1.f / (1.f + expf(-zi));
                float fg = 1.f / (1.f + expf(-zf));
                float og = 1.f / (1.f + expf(-zo));
                float cp = csm[rl * 16 + ul];
                float cn = fg * cp + ig * tanhf(zj);
                float hn = og * tanhf(cn);
                csm[rl * 16 + ul] = cn;

                int grow = m0 + rl;
                int gu   = (n0 >> 2) + ul;
                hout[(size_t)grow * HID + gu] = hn;
                seq_out[((size_t)grow * SEQ + t) * HID + gu] = hn;
            }
        }

        // --- grid barrier ---------------------------------------------------
        __syncthreads();
        if (tid == 0) {
            __threadfence();
            unsigned int old = atomicAdd(&g_bar_count, 1);
            if (old == NCTA - 1) {
                g_bar_count = 0;
                __threadfence();
                atomicAdd(&g_bar_phase, 1);
            } else {
                while (ld_acq(&g_bar_phase) == phase) { }
            }
            phase++;
        }
        __syncthreads();
    }
}

// ---------------------------------------------------------------------------
// SELU
// ---------------------------------------------------------------------------
__device__ __forceinline__ float selu_f(float x) {
    const float sc = 1.0507009873554805f;
    const float al = 1.6732632423543772f;
    return x > 0.f ? sc * x : sc * al * expm1f(x);
}

// ---------------------------------------------------------------------------
// Head fp32 GEMM (tiny)
// ---------------------------------------------------------------------------
template <bool BIAS, bool SELU>
__global__ void __launch_bounds__(256, 2)
sgemm128(const float* __restrict__ A, const float* __restrict__ B,
         float* __restrict__ C, int M, int N, int K,
         const float* __restrict__ bias) {
    __shared__ float As[16][128];
    __shared__ float Bs[16][128];

    const int bm  = blockIdx.y * 128;
    const int bn  = blockIdx.x * 128;
    const int tid = threadIdx.x;
    const int tx  = (tid & 15) * 8;
    const int ty  = (tid >> 4) * 8;

    float acc[8][8] = {};

    const int arow = tid >> 2;
    const int acol = (tid & 3) << 2;
    const int brow = tid >> 5;
    const int bcol = (tid & 31) << 2;

    const float* Aptr = A + (size_t)(bm + arow) * K + acol;
    const float* Bptr = B + (size_t)brow * N + bn + bcol;

    for (int k0 = 0; k0 < K; k0 += 16) {
        float4 a0 = *(const float4*)(Aptr);
        float4 a1 = *(const float4*)(Aptr + (size_t)64 * K);
        float4 b0 = *(const float4*)(Bptr);
        float4 b1 = *(const float4*)(Bptr + (size_t)8 * N);

        As[acol + 0][arow]      = a0.x;
        As[acol + 1][arow]      = a0.y;
        As[acol + 2][arow]      = a0.z;
        As[acol + 3][arow]      = a0.w;
        As[acol + 0][arow + 64] = a1.x;
        As[acol + 1][arow + 64] = a1.y;
        As[acol + 2][arow + 64] = a1.z;
        As[acol + 3][arow + 64] = a1.w;
        *(float4*)&Bs[brow][bcol]     = b0;
        *(float4*)&Bs[brow + 8][bcol] = b1;
        __syncthreads();

        #pragma unroll
        for (int kk = 0; kk < 16; kk++) {
            float ar[8], br[8];
            *(float4*)(ar)     = *(const float4*)&As[kk][ty];
            *(float4*)(ar + 4) = *(const float4*)&As[kk][ty + 4];
            *(float4*)(br)     = *(const float4*)&Bs[kk][tx];
            *(float4*)(br + 4) = *(const float4*)&Bs[kk][tx + 4];
            #pragma unroll
            for (int i = 0; i < 8; i++)
                #pragma unroll
                for (int j = 0; j < 8; j++)
                    acc[i][j] += ar[i] * br[j];
        }
        __syncthreads();

        Aptr += 16;
        Bptr += (size_t)16 * N;
    }

    float bv[8];
    if (BIAS) {
        #pragma unroll
        for (int j = 0; j < 8; j++) bv[j] = bias[bn + tx + j];
    }

    #pragma unroll
    for (int i = 0; i < 8; i++) {
        float v[8];
        #pragma unroll
        for (int j = 0; j < 8; j++) {
            float x = acc[i][j];
            if (BIAS) x += bv[j];
            if (SELU) x = selu_f(x);
            v[j] = x;
        }
        float* crow = C + (size_t)(bm + ty + i) * N + bn + tx;
        *(float4*)(crow)     = *(float4*)(v);
        *(float4*)(crow + 4) = *(float4*)(v + 4);
    }
}

// ---------------------------------------------------------------------------
// BatchNorm / misc head kernels
// ---------------------------------------------------------------------------
__global__ void bn1_kernel(const float* __restrict__ h, const float* __restrict__ gamma,
                           const float* __restrict__ beta, float* __restrict__ y) {
    int f = blockIdx.x;
    int r = threadIdx.x;
    int s = f >> 9;
    int j = f & 511;
    float v = h[((size_t)(s * BATCH + r)) * HID + j];

    __shared__ float sd[256];
    sd[r] = v; __syncthreads();
    for (int w = 128; w > 0; w >>= 1) { if (r < w) sd[r] += sd[r + w]; __syncthreads(); }
    float mu = sd[0] * (1.f / 256.f);
    __syncthreads();
    float d = v - mu;
    sd[r] = d * d; __syncthreads();
    for (int w = 128; w > 0; w >>= 1) { if (r < w) sd[r] += sd[r + w]; __syncthreads(); }
    float var = sd[0] * (1.f / 256.f);

    float sc = gamma[f] * rsqrtf(var + 1e-3f);
    y[r * 1536 + f] = d * sc + beta[f];
}

__global__ void bn_kernel(const float* __restrict__ x, const float* __restrict__ gamma,
                          const float* __restrict__ beta, float* __restrict__ y,
                          int stride) {
    int f = blockIdx.x;
    int r = threadIdx.x;
    float v = x[(size_t)r * stride + f];

    __shared__ float sd[256];
    sd[r] = v; __syncthreads();
    for (int w = 128; w > 0; w >>= 1) { if (r < w) sd[r] += sd[r + w]; __syncthreads(); }
    float mu = sd[0] * (1.f / 256.f);
    __syncthreads();
    float d = v - mu;
    sd[r] = d * d; __syncthreads();
    for (int w = 128; w > 0; w >>= 1) { if (r < w) sd[r] += sd[r + w]; __syncthreads(); }
    float var = sd[0] * (1.f / 256.f);

    float sc = gamma[f] * rsqrtf(var + 1e-3f);
    y[(size_t)r * stride + f] = d * sc + beta[f];
}

__global__ void pad_w2(const float* __restrict__ W2, const float* __restrict__ b2,
                       float* __restrict__ w2p, float* __restrict__ b2p) {
    int idx = blockIdx.x * 256 + threadIdx.x;
    int n = idx & 127;
    int k = idx >> 7;
    w2p[idx] = (n < 102) ? W2[k * 102 + n] : 0.f;
    if (idx < 128) b2p[idx] = (idx < 102) ? b2[idx] : 0.f;
}

__global__ void out_kernel(const float* __restrict__ a, const float* __restrict__ W3,
                           const float* __restrict__ b3, float* __restrict__ out) {
    int idx = blockIdx.x * 256 + threadIdx.x;
    int b = idx >> 2;
    int n = idx & 3;
    float acc = b3[n];
    #pragma unroll 6
    for (int k = 0; k < 102; k++)
        acc += a[b * 128 + k] * W3[k * 4 + n];
    out[idx] = acc;
}

// ---------------------------------------------------------------------------
// Launch
// ---------------------------------------------------------------------------
extern "C" void kernel_launch(void* const* d_in, const int* in_sizes, int n_in,
                              void* d_out, int out_size) {
    const int*   t1   = (const int*)d_in[0];
    const int*   t2   = (const int*)d_in[1];
    const int*   t3   = (const int*)d_in[2];
    const float* emb  = (const float*)d_in[3];
    const float* lw   = (const float*)d_in[4];
    const float* lb   = (const float*)d_in[5];
    const float* bn1g = (const float*)d_in[6];
    const float* bn1b = (const float*)d_in[7];
    const float* W1   = (const float*)d_in[8];
    const float* b1   = (const float*)d_in[9];
    const float* bn2g = (const float*)d_in[10];
    const float* bn2b = (const float*)d_in[11];
    const float* W2   = (const float*)d_in[12];
    const float* b2   = (const float*)d_in[13];
    const float* bn3g = (const float*)d_in[14];
    const float* bn3b = (const float*)d_in[15];
    const float* W3   = (const float*)d_in[16];
    const float* b3   = (const float*)d_in[17];
    float* out = (float*)d_out;

    float *seqA, *seqB, *gx, *h1, *h2, *wxp, *whp, *bp;
    float *xn1, *a1, *xn2, *w2p, *b2p, *a2, *a2n;
    cudaGetSymbolAddress((void**)&seqA, g_seqA);
    cudaGetSymbolAddress((void**)&seqB, g_seqB);
    cudaGetSymbolAddress((void**)&gx,   g_gx);
    cudaGetSymbolAddress((void**)&h1,   g_h1);
    cudaGetSymbolAddress((void**)&h2,   g_h2);
    cudaGetSymbolAddress((void**)&wxp,  g_Wxp);
    cudaGetSymbolAddress((void**)&whp,  g_Whp);
    cudaGetSymbolAddress((void**)&bp,   g_bp);
    cudaGetSymbolAddress((void**)&xn1,  g_xn1);
    cudaGetSymbolAddress((void**)&a1,   g_a1);
    cudaGetSymbolAddress((void**)&xn2,  g_xn2);
    cudaGetSymbolAddress((void**)&w2p,  g_W2p);
    cudaGetSymbolAddress((void**)&b2p,  g_b2p);
    cudaGetSymbolAddress((void**)&a2,   g_a2);
    cudaGetSymbolAddress((void**)&a2n,  g_a2n);

    cudaFuncSetAttribute(lstm_layer, cudaFuncAttributeMaxDynamicSharedMemorySize,
                         SMEM_BYTES);

    prep_kernel<<<(3 * 1024 * G4) / 256, 256>>>(lw, lb, wxp, whp, bp);
    embed_kernel<<<BB * SEQ, 128>>>(t1, t2, t3, emb, seqA);

    float* cur = seqA;
    float* nxt = seqB;
    for (int l = 0; l < 3; l++) {
        const float* Wxl = wxp + (size_t)l * HID * G4;
        const float* Whl = whp + (size_t)l * HID * G4;
        const float* bl  = bp + l * G4;

        gemm_x_tf32<<<dim3(G4 / 128, (BB * SEQ) / 128), 256>>>(cur, Wxl, bl, gx);

        // Persistent recurrence: step t reads hbuf[t&1], writes hbuf[(t+1)&1].
        // t=0 skips the GEMM (h==0), so no h init needed; final h lands in h1.
        lstm_layer<<<NCTA, 256, SMEM_BYTES>>>(Whl, gx, h1, h2, nxt);

        float* tmp = cur; cur = nxt; nxt = tmp;
    }

    bn1_kernel<<<1536, 256>>>(h1, bn1g, bn1b, xn1);
    sgemm128<true, true><<<dim3(1024 / 128, BATCH / 128), 256>>>(
        xn1, W1, a1, BATCH, 1024, 1536, b1);
    bn_kernel<<<1024, 256>>>(a1, bn2g, bn2b, xn2, 1024);
    pad_w2<<<(1024 * 128) / 256, 256>>>(W2, b2, w2p, b2p);
    sgemm128<true, true><<<dim3(1, BATCH / 128), 256>>>(
        xn2, w2p, a2, BATCH, 128, 1024, b2p);
    bn_kernel<<<102, 256>>>(a2, bn3g, bn3b, a2n, 128);
    out_kernel<<<4, 256>>>(a2n, W3, b3, out);
}

// round 4
// speedup vs baseline: 2.1486x; 1.0746x over previous
#include <cuda_runtime.h>
#include <math.h>
#include <stdint.h>

// ---------------------------------------------------------------------------
// Problem constants
// ---------------------------------------------------------------------------
static constexpr int BATCH = 256;
static constexpr int SEQ   = 128;
static constexpr int HID   = 512;
static constexpr int G4    = 2048;
static constexpr int BB    = 768;

// Persistent recurrence config
static constexpr int NCTA    = 128;            // 4 M-blocks x 32 N-slices
static constexpr int M_TILE  = 192;
static constexpr int N_TILE  = 64;
static constexpr int A_KG    = M_TILE * 8 + 8;           // padded kg stride (words)
static constexpr int SMEM_B_WORDS = 64 * 512;            // 32768
static constexpr int SMEM_A_WORDS = 2 * 4 * A_KG;        // 12352
static constexpr int SMEM_C_WORDS = M_TILE * 16;         // 3072
static constexpr int SMEM_BYTES   = (SMEM_B_WORDS + SMEM_A_WORDS + SMEM_C_WORDS) * 4;

// ---------------------------------------------------------------------------
// Scratch (device globals; no runtime allocation allowed)
// ---------------------------------------------------------------------------
__device__ float    g_seqA[(size_t)BB * SEQ * HID];
__device__ float    g_seqB[(size_t)BB * SEQ * HID];
__device__ float    g_gx  [(size_t)BB * SEQ * G4];   // fragment-native layout
__device__ uint32_t g_hP0 [(size_t)BB * HID];        // packed tf32 h ping
__device__ uint32_t g_hP1 [(size_t)BB * HID];        // packed tf32 h pong
__device__ float    g_hf  [(size_t)BB * HID];        // exact fp32 final h
__device__ float    g_Wxp [(size_t)3 * HID * G4];
__device__ float    g_Whp [(size_t)3 * HID * G4];
__device__ float    g_bp  [3 * G4];
__device__ float    g_xn1 [BATCH * 1536];
__device__ float    g_a1  [BATCH * 1024];
__device__ float    g_xn2 [BATCH * 1024];
__device__ float    g_W2p [1024 * 128];
__device__ float    g_b2p [128];
__device__ float    g_a2  [BATCH * 128];
__device__ float    g_a2n [BATCH * 128];

// Grid barrier state (monotonic phase; graph-replay safe)
__device__ unsigned int g_bar_count;
__device__ unsigned int g_bar_phase;

// ---------------------------------------------------------------------------
// TF32 helpers
// ---------------------------------------------------------------------------
__device__ __forceinline__ uint32_t tf32r(float x) {
    uint32_t u;
    asm("cvt.rna.tf32.f32 %0, %1;" : "=r"(u) : "f"(x));
    return u;
}

__device__ __forceinline__ void mma8(float* c, const uint32_t* a, const uint32_t* b) {
    asm volatile(
        "mma.sync.aligned.m16n8k8.row.col.f32.tf32.tf32.f32 "
        "{%0,%1,%2,%3}, {%4,%5,%6,%7}, {%8,%9}, {%0,%1,%2,%3};"
        : "+f"(c[0]), "+f"(c[1]), "+f"(c[2]), "+f"(c[3])
        : "r"(a[0]), "r"(a[1]), "r"(a[2]), "r"(a[3]), "r"(b[0]), "r"(b[1]));
}

__device__ __forceinline__ unsigned int ld_acq(const unsigned int* p) {
    unsigned int v;
    asm volatile("ld.acquire.gpu.u32 %0, [%1];" : "=r"(v) : "l"(p));
    return v;
}

// ---------------------------------------------------------------------------
// gx fragment-native address mapping.
// Consumer (lstm_layer): CTA bx = mb*32+nb (tiles 192x64), warp = wm_i*2+wn_i
// (warp tile 48x32), lane = p*4+q, 24 float2 slots = (mf*4+nf)*2 + half.
// ---------------------------------------------------------------------------
__device__ __forceinline__ void store_gx_frag(float* gxL, int r, int n, float2 v) {
    int t   = r & 127, row = r >> 7;
    int mb  = row / 192, rl = row - mb * 192;
    int wmi = rl / 48,  rlp = rl - wmi * 48;
    int mfl = rlp >> 4, pp = rlp & 15;
    int nb  = n >> 6,   ncl = n & 63;
    int wni = ncl >> 5, ncl2 = ncl & 31;
    int nfl = ncl2 >> 3, ql = (ncl2 & 7) >> 1;
    size_t idx = ((((size_t)t * 128 + mb * 32 + nb) * 8 + wmi * 2 + wni) * 32
                  + (pp & 7) * 4 + ql) * 24 + (mfl * 4 + nfl) * 2 + (pp >> 3);
    *(float2*)(gxL + idx * 2) = v;
}

// ---------------------------------------------------------------------------
// Embedding gather
// ---------------------------------------------------------------------------
__global__ void embed_kernel(const int* __restrict__ t1, const int* __restrict__ t2,
                             const int* __restrict__ t3, const float* __restrict__ emb,
                             float* __restrict__ out) {
    int bbt = blockIdx.x;
    int bb  = bbt >> 7;
    int t   = bbt & 127;
    int s   = bb >> 8;
    int b   = bb & 255;
    const int* txt = (s == 0) ? t1 : (s == 1 ? t2 : t3);
    int tok = txt[b * SEQ + t];
    const float4* src = (const float4*)(emb + (size_t)tok * HID);
    float4*       dst = (float4*)(out + (size_t)bbt * HID);
    dst[threadIdx.x] = src[threadIdx.x];
}

// ---------------------------------------------------------------------------
// Weight/bias permutation into gate-interleaved layout
// ---------------------------------------------------------------------------
__global__ void prep_kernel(const float* __restrict__ lw, const float* __restrict__ lb,
                            float* __restrict__ wxp, float* __restrict__ whp,
                            float* __restrict__ bp) {
    int idx = blockIdx.x * 256 + threadIdx.x;
    int l   = idx / (1024 * G4);
    int rem = idx - l * 1024 * G4;
    int k   = rem / G4;
    int n   = rem - k * G4;
    int u   = n >> 2, g = n & 3;
    float v = lw[(size_t)l * 1024 * G4 + (size_t)k * G4 + g * HID + u];
    if (k < HID) wxp[(size_t)l * HID * G4 + (size_t)k * G4 + n] = v;
    else         whp[(size_t)l * HID * G4 + (size_t)(k - HID) * G4 + n] = v;
    if (idx < 3 * G4) {
        int ll = idx / G4, nn = idx - ll * G4;
        bp[idx] = lb[ll * G4 + (nn & 3) * HID + (nn >> 2)];
    }
}

// ---------------------------------------------------------------------------
// Big parallel x-GEMM (tf32 tensor cores); epilogue writes fragment-native gx.
// ---------------------------------------------------------------------------
__global__ void __launch_bounds__(256, 2)
gemm_x_tf32(const float* __restrict__ A, const float* __restrict__ B,
            const float* __restrict__ bias, float* __restrict__ gxL) {
    __shared__ uint32_t As[128][33];
    __shared__ uint32_t Bs[32][129];

    const int tid  = threadIdx.x;
    const int lane = tid & 31, warp = tid >> 5;
    const int wm   = (warp >> 1) * 32, wn = (warp & 1) * 64;
    const int bm   = blockIdx.y * 128, bn = blockIdx.x * 128;

    float acc[2][8][4] = {};

    const int alr = tid >> 3,  alc = (tid & 7) << 2;
    const int blr = tid >> 5,  blc = (tid & 31) << 2;

    for (int kt = 0; kt < 512; kt += 32) {
        #pragma unroll
        for (int pp = 0; pp < 4; pp++) {
            int r = alr + pp * 32;
            float4 v = *(const float4*)(A + (size_t)(bm + r) * 512 + kt + alc);
            As[r][alc + 0] = tf32r(v.x); As[r][alc + 1] = tf32r(v.y);
            As[r][alc + 2] = tf32r(v.z); As[r][alc + 3] = tf32r(v.w);
        }
        #pragma unroll
        for (int pp = 0; pp < 4; pp++) {
            int r = blr + pp * 8;
            float4 v = *(const float4*)(B + (size_t)(kt + r) * G4 + bn + blc);
            Bs[r][blc + 0] = tf32r(v.x); Bs[r][blc + 1] = tf32r(v.y);
            Bs[r][blc + 2] = tf32r(v.z); Bs[r][blc + 3] = tf32r(v.w);
        }
        __syncthreads();

        #pragma unroll
        for (int ks = 0; ks < 4; ks++) {
            const int k0 = ks * 8;
            uint32_t af[2][4], bf[8][2];
            #pragma unroll
            for (int mf = 0; mf < 2; mf++) {
                int r = wm + mf * 16 + (lane >> 2), c = k0 + (lane & 3);
                af[mf][0] = As[r][c];     af[mf][1] = As[r + 8][c];
                af[mf][2] = As[r][c + 4]; af[mf][3] = As[r + 8][c + 4];
            }
            #pragma unroll
            for (int nf = 0; nf < 8; nf++) {
                int n = wn + nf * 8 + (lane >> 2);
                bf[nf][0] = Bs[k0 + (lane & 3)][n];
                bf[nf][1] = Bs[k0 + 4 + (lane & 3)][n];
            }
            #pragma unroll
            for (int mf = 0; mf < 2; mf++)
                #pragma unroll
                for (int nf = 0; nf < 8; nf++)
                    mma8(acc[mf][nf], af[mf], bf[nf]);
        }
        __syncthreads();
    }

    const int q = lane & 3;
    const int pr = lane >> 2;
    #pragma unroll
    for (int mf = 0; mf < 2; mf++) {
        int r = bm + wm + mf * 16 + pr;
        #pragma unroll
        for (int nf = 0; nf < 8; nf++) {
            int n = bn + wn + nf * 8 + 2 * q;
            float b0 = bias[n], b1 = bias[n + 1];
            float2 v0 = make_float2(acc[mf][nf][0] + b0, acc[mf][nf][1] + b1);
            float2 v1 = make_float2(acc[mf][nf][2] + b0, acc[mf][nf][3] + b1);
            store_gx_frag(gxL, r,     n, v0);
            store_gx_frag(gxL, r + 8, n, v1);
        }
    }
}

// ---------------------------------------------------------------------------
// Persistent LSTM layer. 128 CTAs x 256 thr; CTA tile 192x64.
// h in global as packed tf32 (mma k-order); gx fragment-native (coalesced);
// single-sync pipelined A copy; c-state in SMEM; grid barrier per step.
// ---------------------------------------------------------------------------
__global__ void __launch_bounds__(256, 1)
lstm_layer(const float* __restrict__ Wh, const float* __restrict__ gx,
           uint32_t* __restrict__ hA, uint32_t* __restrict__ hB,
           float* __restrict__ seq_out, float* __restrict__ h_final, int last) {
    extern __shared__ uint32_t smem[];
    uint32_t* Bp  = smem;
    uint32_t* Ap  = smem + SMEM_B_WORDS;
    float*    csm = (float*)(smem + SMEM_B_WORDS + SMEM_A_WORDS);

    const int tid  = threadIdx.x;
    const int lane = tid & 31, warp = tid >> 5;
    const int q    = lane & 3;
    const int p    = lane >> 2;
    const int wm   = (warp >> 1) * 48;
    const int wn   = (warp & 1) * 32;
    const int m0   = (blockIdx.x >> 5) * M_TILE;
    const int n0   = (blockIdx.x & 31) * N_TILE;

    unsigned int phase = 0;
    if (tid == 0) phase = ld_acq(&g_bar_phase);

    // Pack B slice (once per layer): Bp[kg*512 + col*8 + slot]
    for (int i = tid; i < 512 * 16; i += 256) {
        int k = i >> 4, cg = i & 15;
        float4 v = *(const float4*)(Wh + (size_t)k * G4 + n0 + cg * 4);
        int kg = k >> 3, kk = k & 7;
        int base = kg * 512 + (kk & 3) * 2 + (kk >> 2);
        Bp[base + (cg * 4 + 0) * 8] = tf32r(v.x);
        Bp[base + (cg * 4 + 1) * 8] = tf32r(v.y);
        Bp[base + (cg * 4 + 2) * 8] = tf32r(v.z);
        Bp[base + (cg * 4 + 3) * 8] = tf32r(v.w);
    }
    for (int i = tid; i < SMEM_C_WORDS; i += 256) csm[i] = 0.f;
    __syncthreads();

    const int srow = tid >> 3, scg = tid & 7;   // A-copy thread mapping

    for (int t = 0; t < SEQ; t++) {
        const uint32_t* hin  = (t & 1) ? hB : hA;
        uint32_t*       hout = (t & 1) ? hA : hB;

        // Prefetch this step's gx fragments (coalesced; 12x LDG.128).
        float4 gxv[12];
        {
            const float4* gp = (const float4*)gx +
                ((((size_t)t * 128 + blockIdx.x) * 8 + warp) * 32 + lane) * 12;
            #pragma unroll
            for (int j = 0; j < 12; j++) gxv[j] = gp[j];
        }

        float acc[3][4][4] = {};

        if (t > 0) {
            uint4 v[6];
            #pragma unroll
            for (int i = 0; i < 6; i++) {
                int row = srow + i * 32;
                v[i] = __ldcg((const uint4*)hin + (size_t)(m0 + row) * 128 + scg);
            }
            #pragma unroll 1
            for (int ct = 0; ct <= 16; ct++) {
                __syncthreads();
                if (ct < 16) {
                    uint32_t* Ab = Ap + (ct & 1) * (4 * A_KG);
                    #pragma unroll
                    for (int i = 0; i < 6; i++) {
                        int row = srow + i * 32;
                        *(uint4*)(Ab + (scg >> 1) * A_KG + row * 8 + (scg & 1) * 4) = v[i];
                    }
                }
                if (ct < 15) {
                    #pragma unroll
                    for (int i = 0; i < 6; i++) {
                        int row = srow + i * 32;
                        v[i] = __ldcg((const uint4*)hin + (size_t)(m0 + row) * 128
                                      + (ct + 1) * 8 + scg);
                    }
                }
                if (ct >= 1) {
                    const uint32_t* Ab = Ap + ((ct - 1) & 1) * (4 * A_KG);
                    #pragma unroll
                    for (int kgl = 0; kgl < 4; kgl++) {
                        const int kg = (ct - 1) * 4 + kgl;
                        uint32_t af[3][4];
                        #pragma unroll
                        for (int mf = 0; mf < 3; mf++) {
                            int rl = wm + mf * 16 + p;
                            uint2 p0 = *(const uint2*)&Ab[kgl * A_KG + rl * 8 + q * 2];
                            uint2 p1 = *(const uint2*)&Ab[kgl * A_KG + (rl + 8) * 8 + q * 2];
                            af[mf][0] = p0.x; af[mf][1] = p1.x;
                            af[mf][2] = p0.y; af[mf][3] = p1.y;
                        }
                        uint32_t bfr[4][2];
                        #pragma unroll
                        for (int nf = 0; nf < 4; nf++) {
                            int nl = wn + nf * 8 + p;
                            uint2 pb = *(const uint2*)&Bp[kg * 512 + nl * 8 + q * 2];
                            bfr[nf][0] = pb.x; bfr[nf][1] = pb.y;
                        }
                        #pragma unroll
                        for (int mf = 0; mf < 3; mf++)
                            #pragma unroll
                            for (int nf = 0; nf < 4; nf++)
                                mma8(acc[mf][nf], af[mf], bfr[nf]);
                    }
                }
            }
        }

        // Epilogue: z = acc + gx; cell update; packed-tf32 h store.
        #pragma unroll
        for (int mf = 0; mf < 3; mf++) {
            int rl0 = wm + mf * 16 + p;
            int rl1 = rl0 + 8;
            #pragma unroll
            for (int nf = 0; nf < 4; nf++) {
                int ncl = wn + nf * 8 + 2 * q;
                int j   = mf * 4 + nf;
                float z0 = acc[mf][nf][0] + gxv[j].x;
                float z1 = acc[mf][nf][1] + gxv[j].y;
                float z2 = acc[mf][nf][2] + gxv[j].z;
                float z3 = acc[mf][nf][3] + gxv[j].w;
                float o0 = __shfl_xor_sync(0xffffffffu, z0, 1);
                float o1 = __shfl_xor_sync(0xffffffffu, z1, 1);
                float o2 = __shfl_xor_sync(0xffffffffu, z2, 1);
                float o3 = __shfl_xor_sync(0xffffffffu, z3, 1);
                bool evenq = (q & 1) == 0;
                int   rl = evenq ? rl0 : rl1;
                float zi = evenq ? z0 : o2;
                float zj = evenq ? z1 : o3;
                float zf = evenq ? o0 : z2;
                float zo = evenq ? o1 : z3;
                int   ul = ncl >> 2;

                float ig = 1.f / (1.f + expf(-zi));
                float fg = 1.f / (1.f + expf(-zf));
                float og = 1.f / (1.f + expf(-zo));
                float cp = csm[rl * 16 + ul];
                float cn = fg * cp + ig * tanhf(zj);
                float hn = og * tanhf(cn);
                csm[rl * 16 + ul] = cn;

                int grow = m0 + rl;
                int gu   = (n0 >> 2) + ul;
                int kg2  = gu >> 3, kk = gu & 7;
                int slot = (kk & 3) * 2 + (kk >> 2);
                hout[(size_t)grow * HID + kg2 * 8 + slot] = tf32r(hn);
                if (!last)
                    seq_out[((size_t)grow * SEQ + t) * HID + gu] = hn;
                else if (t == SEQ - 1)
                    h_final[(size_t)grow * HID + gu] = hn;
            }
        }

        // Grid barrier
        __syncthreads();
        if (tid == 0) {
            __threadfence();
            unsigned int old = atomicAdd(&g_bar_count, 1);
            if (old == NCTA - 1) {
                g_bar_count = 0;
                __threadfence();
                atomicAdd(&g_bar_phase, 1);
            } else {
                while (ld_acq(&g_bar_phase) == phase) { }
            }
            phase++;
        }
        __syncthreads();
    }
}

// ---------------------------------------------------------------------------
// SELU
// ---------------------------------------------------------------------------
__device__ __forceinline__ float selu_f(float x) {
    const float sc = 1.0507009873554805f;
    const float al = 1.6732632423543772f;
    return x > 0.f ? sc * x : sc * al * expm1f(x);
}

// ---------------------------------------------------------------------------
// Head fp32 GEMM (tiny)
// ---------------------------------------------------------------------------
template <bool BIAS, bool SELU>
__global__ void __launch_bounds__(256, 2)
sgemm128(const float* __restrict__ A, const float* __restrict__ B,
         float* __restrict__ C, int M, int N, int K,
         const float* __restrict__ bias) {
    __shared__ float As[16][128];
    __shared__ float Bs[16][128];

    const int bm  = blockIdx.y * 128;
    const int bn  = blockIdx.x * 128;
    const int tid = threadIdx.x;
    const int tx  = (tid & 15) * 8;
    const int ty  = (tid >> 4) * 8;

    float acc[8][8] = {};

    const int arow = tid >> 2;
    const int acol = (tid & 3) << 2;
    const int brow = tid >> 5;
    const int bcol = (tid & 31) << 2;

    const float* Aptr = A + (size_t)(bm + arow) * K + acol;
    const float* Bptr = B + (size_t)brow * N + bn + bcol;

    for (int k0 = 0; k0 < K; k0 += 16) {
        float4 a0 = *(const float4*)(Aptr);
        float4 a1 = *(const float4*)(Aptr + (size_t)64 * K);
        float4 b0 = *(const float4*)(Bptr);
        float4 b1 = *(const float4*)(Bptr + (size_t)8 * N);

        As[acol + 0][arow]      = a0.x;
        As[acol + 1][arow]      = a0.y;
        As[acol + 2][arow]      = a0.z;
        As[acol + 3][arow]      = a0.w;
        As[acol + 0][arow + 64] = a1.x;
        As[acol + 1][arow + 64] = a1.y;
        As[acol + 2][arow + 64] = a1.z;
        As[acol + 3][arow + 64] = a1.w;
        *(float4*)&Bs[brow][bcol]     = b0;
        *(float4*)&Bs[brow + 8][bcol] = b1;
        __syncthreads();

        #pragma unroll
        for (int kk = 0; kk < 16; kk++) {
            float ar[8], br[8];
            *(float4*)(ar)     = *(const float4*)&As[kk][ty];
            *(float4*)(ar + 4) = *(const float4*)&As[kk][ty + 4];
            *(float4*)(br)     = *(const float4*)&Bs[kk][tx];
            *(float4*)(br + 4) = *(const float4*)&Bs[kk][tx + 4];
            #pragma unroll
            for (int i = 0; i < 8; i++)
                #pragma unroll
                for (int j = 0; j < 8; j++)
                    acc[i][j] += ar[i] * br[j];
        }
        __syncthreads();

        Aptr += 16;
        Bptr += (size_t)16 * N;
    }

    float bv[8];
    if (BIAS) {
        #pragma unroll
        for (int j = 0; j < 8; j++) bv[j] = bias[bn + tx + j];
    }

    #pragma unroll
    for (int i = 0; i < 8; i++) {
        float v[8];
        #pragma unroll
        for (int j = 0; j < 8; j++) {
            float x = acc[i][j];
            if (BIAS) x += bv[j];
            if (SELU) x = selu_f(x);
            v[j] = x;
        }
        float* crow = C + (size_t)(bm + ty + i) * N + bn + tx;
        *(float4*)(crow)     = *(float4*)(v);
        *(float4*)(crow + 4) = *(float4*)(v + 4);
    }
}

// ---------------------------------------------------------------------------
// BatchNorm / misc head kernels
// ---------------------------------------------------------------------------
__global__ void bn1_kernel(const float* __restrict__ h, const float* __restrict__ gamma,
                           const float* __restrict__ beta, float* __restrict__ y) {
    int f = blockIdx.x;
    int r = threadIdx.x;
    int s = f >> 9;
    int j = f & 511;
    float v = h[((size_t)(s * BATCH + r)) * HID + j];

    __shared__ float sd[256];
    sd[r] = v; __syncthreads();
    for (int w = 128; w > 0; w >>= 1) { if (r < w) sd[r] += sd[r + w]; __syncthreads(); }
    float mu = sd[0] * (1.f / 256.f);
    __syncthreads();
    float d = v - mu;
    sd[r] = d * d; __syncthreads();
    for (int w = 128; w > 0; w >>= 1) { if (r < w) sd[r] += sd[r + w]; __syncthreads(); }
    float var = sd[0] * (1.f / 256.f);

    float sc = gamma[f] * rsqrtf(var + 1e-3f);
    y[r * 1536 + f] = d * sc + beta[f];
}

__global__ void bn_kernel(const float* __restrict__ x, const float* __restrict__ gamma,
                          const float* __restrict__ beta, float* __restrict__ y,
                          int stride) {
    int f = blockIdx.x;
    int r = threadIdx.x;
    float v = x[(size_t)r * stride + f];

    __shared__ float sd[256];
    sd[r] = v; __syncthreads();
    for (int w = 128; w > 0; w >>= 1) { if (r < w) sd[r] += sd[r + w]; __syncthreads(); }
    float mu = sd[0] * (1.f / 256.f);
    __syncthreads();
    float d = v - mu;
    sd[r] = d * d; __syncthreads();
    for (int w = 128; w > 0; w >>= 1) { if (r < w) sd[r] += sd[r + w]; __syncthreads(); }
    float var = sd[0] * (1.f / 256.f);

    float sc = gamma[f] * rsqrtf(var + 1e-3f);
    y[(size_t)r * stride + f] = d * sc + beta[f];
}

__global__ void pad_w2(const float* __restrict__ W2, const float* __restrict__ b2,
                       float* __restrict__ w2p, float* __restrict__ b2p) {
    int idx = blockIdx.x * 256 + threadIdx.x;
    int n = idx & 127;
    int k = idx >> 7;
    w2p[idx] = (n < 102) ? W2[k * 102 + n] : 0.f;
    if (idx < 128) b2p[idx] = (idx < 102) ? b2[idx] : 0.f;
}

__global__ void out_kernel(const float* __restrict__ a, const float* __restrict__ W3,
                           const float* __restrict__ b3, float* __restrict__ out) {
    int idx = blockIdx.x * 256 + threadIdx.x;
    int b = idx >> 2;
    int n = idx & 3;
    float acc = b3[n];
    #pragma unroll 6
    for (int k = 0; k < 102; k++)
        acc += a[b * 128 + k] * W3[k * 4 + n];
    out[idx] = acc;
}

// ---------------------------------------------------------------------------
// Launch
// ---------------------------------------------------------------------------
extern "C" void kernel_launch(void* const* d_in, const int* in_sizes, int n_in,
                              void* d_out, int out_size) {
    const int*   t1   = (const int*)d_in[0];
    const int*   t2   = (const int*)d_in[1];
    const int*   t3   = (const int*)d_in[2];
    const float* emb  = (const float*)d_in[3];
    const float* lw   = (const float*)d_in[4];
    const float* lb   = (const float*)d_in[5];
    const float* bn1g = (const float*)d_in[6];
    const float* bn1b = (const float*)d_in[7];
    const float* W1   = (const float*)d_in[8];
    const float* b1   = (const float*)d_in[9];
    const float* bn2g = (const float*)d_in[10];
    const float* bn2b = (const float*)d_in[11];
    const float* W2   = (const float*)d_in[12];
    const float* b2   = (const float*)d_in[13];
    const float* bn3g = (const float*)d_in[14];
    const float* bn3b = (const float*)d_in[15];
    const float* W3   = (const float*)d_in[16];
    const float* b3   = (const float*)d_in[17];
    float* out = (float*)d_out;

    float *seqA, *seqB, *gx, *hf, *wxp, *whp, *bp;
    uint32_t *hP0, *hP1;
    float *xn1, *a1, *xn2, *w2p, *b2p, *a2, *a2n;
    cudaGetSymbolAddress((void**)&seqA, g_seqA);
    cudaGetSymbolAddress((void**)&seqB, g_seqB);
    cudaGetSymbolAddress((void**)&gx,   g_gx);
    cudaGetSymbolAddress((void**)&hP0,  g_hP0);
    cudaGetSymbolAddress((void**)&hP1,  g_hP1);
    cudaGetSymbolAddress((void**)&hf,   g_hf);
    cudaGetSymbolAddress((void**)&wxp,  g_Wxp);
    cudaGetSymbolAddress((void**)&whp,  g_Whp);
    cudaGetSymbolAddress((void**)&bp,   g_bp);
    cudaGetSymbolAddress((void**)&xn1,  g_xn1);
    cudaGetSymbolAddress((void**)&a1,   g_a1);
    cudaGetSymbolAddress((void**)&xn2,  g_xn2);
    cudaGetSymbolAddress((void**)&w2p,  g_W2p);
    cudaGetSymbolAddress((void**)&b2p,  g_b2p);
    cudaGetSymbolAddress((void**)&a2,   g_a2);
    cudaGetSymbolAddress((void**)&a2n,  g_a2n);

    cudaFuncSetAttribute(lstm_layer, cudaFuncAttributeMaxDynamicSharedMemorySize,
                         SMEM_BYTES);

    prep_kernel<<<(3 * 1024 * G4) / 256, 256>>>(lw, lb, wxp, whp, bp);
    embed_kernel<<<BB * SEQ, 128>>>(t1, t2, t3, emb, seqA);

    float* cur = seqA;
    float* nxt = seqB;
    for (int l = 0; l < 3; l++) {
        const float* Wxl = wxp + (size_t)l * HID * G4;
        const float* Whl = whp + (size_t)l * HID * G4;
        const float* bl  = bp + l * G4;

        gemm_x_tf32<<<dim3(G4 / 128, (BB * SEQ) / 128), 256>>>(cur, Wxl, bl, gx);

        lstm_layer<<<NCTA, 256, SMEM_BYTES>>>(Whl, gx, hP0, hP1, nxt, hf, l == 2);

        float* tmp = cur; cur = nxt; nxt = tmp;
    }

    bn1_kernel<<<1536, 256>>>(hf, bn1g, bn1b, xn1);
    sgemm128<true, true><<<dim3(1024 / 128, BATCH / 128), 256>>>(
        xn1, W1, a1, BATCH, 1024, 1536, b1);
    bn_kernel<<<1024, 256>>>(a1, bn2g, bn2b, xn2, 1024);
    pad_w2<<<(1024 * 128) / 256, 256>>>(W2, b2, w2p, b2p);
    sgemm128<true, true><<<dim3(1, BATCH / 128), 256>>>(
        xn2, w2p, a2, BATCH, 128, 1024, b2p);
    bn_kernel<<<102, 256>>>(a2, bn3g, bn3b, a2n, 128);
    out_kernel<<<4, 256>>>(a2n, W3, b3, out);
}